// round 2
// baseline (speedup 1.0000x reference)
#include <cuda_runtime.h>
#include <math.h>

#define N_SPK 2048
#define M_UTT 16
#define D_EMB 512
#define NM (N_SPK * M_UTT)
#define EPSF 1e-8f

// Scratch (allocation-free rule: __device__ globals)
__device__ float g_Cn[N_SPK * D_EMB];     // normalized centroids  [2048,512]
__device__ float g_vn[NM * D_EMB];        // normalized utterances [32768,512]
__device__ float g_sdiag[NM];             // cos(C_min[j], v_j)
__device__ float g_sself[NM];             // cos(C[spk(j)], v_j)  (as GEMM would compute it)
__device__ float g_colsum[NM];            // sum_n exp(w*(S[n,j]-1)) with full-C diag row

// ---------------------------------------------------------------------------
// Init: zero colsum + output (d_out is poisoned before timing; replays must re-zero)
// ---------------------------------------------------------------------------
__global__ void init_kernel(float* out) {
    int i = blockIdx.x * blockDim.x + threadIdx.x;
    if (i < NM) g_colsum[i] = 0.0f;
    if (i == 0) *out = 0.0f;
}

// ---------------------------------------------------------------------------
// Prep: one block per speaker. Computes Cn, vn, S_diag, S_self.
//   sq[m]  = ||v_m||^2
//   dsv[m] = ssum . v_m
//   ss     = ||ssum||^2
//   cm = ssum - v_m:  cm.v = dsv - sq ;  ||cm||^2 = ss - 2 dsv + sq
// ---------------------------------------------------------------------------
__global__ __launch_bounds__(256) void prep_kernel(const float* __restrict__ v) {
    __shared__ float sv[M_UTT * D_EMB];     // 32 KB
    __shared__ float red[8][33];
    __shared__ float fin[33];

    const int tid = threadIdx.x;
    const int n = blockIdx.x;

    // Load this speaker's 16x512 block
    {
        const float4* src = (const float4*)(v + (size_t)n * M_UTT * D_EMB);
        float4* dst = (float4*)sv;
        #pragma unroll
        for (int i = 0; i < (M_UTT * D_EMB / 4) / 256; i++)
            dst[tid + i * 256] = src[tid + i * 256];
    }
    __syncthreads();

    // Thread owns columns d0 = tid, d1 = tid + 256
    float s0 = 0.0f, s1 = 0.0f;
    #pragma unroll
    for (int m = 0; m < M_UTT; m++) {
        s0 += sv[m * D_EMB + tid];
        s1 += sv[m * D_EMB + tid + 256];
    }

    float vals[33];
    #pragma unroll
    for (int m = 0; m < M_UTT; m++) {
        float x0 = sv[m * D_EMB + tid];
        float x1 = sv[m * D_EMB + tid + 256];
        vals[m]      = x0 * x0 + x1 * x1;   // sq partial
        vals[16 + m] = s0 * x0 + s1 * x1;   // dsv partial
    }
    vals[32] = s0 * s0 + s1 * s1;           // ss partial

    // Block reduction of 33 values
    #pragma unroll
    for (int i = 0; i < 33; i++) {
        float x = vals[i];
        #pragma unroll
        for (int o = 16; o > 0; o >>= 1)
            x += __shfl_xor_sync(0xffffffffu, x, o);
        vals[i] = x;
    }
    const int warp = tid >> 5, lane = tid & 31;
    if (lane == 0) {
        #pragma unroll
        for (int i = 0; i < 33; i++) red[warp][i] = vals[i];
    }
    __syncthreads();
    if (tid < 33) {
        float x = 0.0f;
        #pragma unroll
        for (int w = 0; w < 8; w++) x += red[w][tid];
        fin[tid] = x;
    }
    __syncthreads();

    const float ss = fin[32];
    const float rn = sqrtf(ss);
    const float cinv = 1.0f / fmaxf(rn, (float)M_UTT * EPSF);   // normalize(ssum/M) == ssum / max(rn, M*eps)

    g_Cn[n * D_EMB + tid]       = s0 * cinv;
    g_Cn[n * D_EMB + tid + 256] = s1 * cinv;

    #pragma unroll
    for (int m = 0; m < M_UTT; m++) {
        float rv = 1.0f / fmaxf(sqrtf(fin[m]), EPSF);
        size_t base = (size_t)(n * M_UTT + m) * D_EMB;
        g_vn[base + tid]       = sv[m * D_EMB + tid] * rv;
        g_vn[base + tid + 256] = sv[m * D_EMB + tid + 256] * rv;
    }

    if (tid < M_UTT) {
        const int m = tid;
        float sq  = fin[m];
        float dsv = fin[16 + m];
        float nv  = fmaxf(sqrtf(sq), EPSF);
        float cm2 = fmaxf(ss - 2.0f * dsv + sq, 0.0f);
        const float invMm1 = 1.0f / (float)(M_UTT - 1);
        float ncm = fmaxf(sqrtf(cm2) * invMm1, EPSF);
        float sd  = ((dsv - sq) * invMm1) / (ncm * nv);
        // exactly the value the uniform GEMM produces for row spk(j), col j:
        float sf  = (dsv * cinv) / nv;
        g_sdiag[n * M_UTT + m] = sd;
        g_sself[n * M_UTT + m] = sf;
    }
}

// ---------------------------------------------------------------------------
// Fused GEMM + exp epilogue.
// S = Cn @ vn^T, tiles 128x128, threads 256 (16x16 grid of 8x8 micro-tiles).
// colsum[j] += sum_rows exp(w * (S - 1))   [shift by max logit w*1+b -> b cancels]
// ---------------------------------------------------------------------------
__global__ __launch_bounds__(256, 2) void gemm_lse_kernel(const float* __restrict__ wp) {
    __shared__ float As[8][128];
    __shared__ float Bs[8][128];
    __shared__ float csh[128];

    const int tid = threadIdx.x;
    const int rowBase = blockIdx.y * 128;
    const int colBase = blockIdx.x * 128;
    const int tx = tid & 15;          // column group
    const int ty = tid >> 4;          // row group
    const int lr = tid >> 1;          // 0..127: tile row loaded by this thread
    const int lk = (tid & 1) * 4;     // k sub-offset 0 or 4

    const float* Ap = g_Cn + (size_t)(rowBase + lr) * D_EMB + lk;
    const float* Bp = g_vn + (size_t)(colBase + lr) * D_EMB + lk;

    float acc[8][8];
    #pragma unroll
    for (int i = 0; i < 8; i++)
        #pragma unroll
        for (int j = 0; j < 8; j++) acc[i][j] = 0.0f;

    float4 a4 = *(const float4*)Ap;
    float4 b4 = *(const float4*)Bp;

    for (int kt = 8; kt <= D_EMB; kt += 8) {
        __syncthreads();
        As[lk + 0][lr] = a4.x; As[lk + 1][lr] = a4.y;
        As[lk + 2][lr] = a4.z; As[lk + 3][lr] = a4.w;
        Bs[lk + 0][lr] = b4.x; Bs[lk + 1][lr] = b4.y;
        Bs[lk + 2][lr] = b4.z; Bs[lk + 3][lr] = b4.w;
        __syncthreads();
        if (kt < D_EMB) {                 // prefetch next tile into registers
            a4 = *(const float4*)(Ap + kt);
            b4 = *(const float4*)(Bp + kt);
        }
        #pragma unroll
        for (int k = 0; k < 8; k++) {
            float a[8], b[8];
            *(float4*)(a)     = *(const float4*)&As[k][ty * 8];
            *(float4*)(a + 4) = *(const float4*)&As[k][ty * 8 + 4];
            *(float4*)(b)     = *(const float4*)&Bs[k][tx * 8];
            *(float4*)(b + 4) = *(const float4*)&Bs[k][tx * 8 + 4];
            #pragma unroll
            for (int i = 0; i < 8; i++)
                #pragma unroll
                for (int j = 0; j < 8; j++)
                    acc[i][j] += a[i] * b[j];
        }
    }

    // Epilogue: per-column sum of exp(w*(S-1)) over this tile's 128 rows
    if (tid < 128) csh[tid] = 0.0f;
    const float wv = *wp;
    __syncthreads();
    #pragma unroll
    for (int j = 0; j < 8; j++) {
        float s = 0.0f;
        #pragma unroll
        for (int i = 0; i < 8; i++)
            s += __expf(wv * (acc[i][j] - 1.0f));
        atomicAdd(&csh[tx * 8 + j], s);
    }
    __syncthreads();
    if (tid < 128) atomicAdd(&g_colsum[colBase + tid], csh[tid]);
}

// ---------------------------------------------------------------------------
// Final loss:
//   csum_j = colsum_j - exp(w*(S_self-1)) + exp(w*(S_diag-1))
//   L_j    = w*(1 - S_diag_j) + log(csum_j)        (b cancels)
// ---------------------------------------------------------------------------
__global__ __launch_bounds__(256) void loss_kernel(const float* __restrict__ wp,
                                                   float* __restrict__ out) {
    __shared__ float rs[8];
    const int j = blockIdx.x * blockDim.x + threadIdx.x;
    const float wv = *wp;
    float L = 0.0f;
    if (j < NM) {
        float sd = g_sdiag[j];
        float sf = g_sself[j];
        float cs = g_colsum[j] - __expf(wv * (sf - 1.0f)) + __expf(wv * (sd - 1.0f));
        L = wv * (1.0f - sd) + logf(cs);
    }
    #pragma unroll
    for (int o = 16; o > 0; o >>= 1)
        L += __shfl_xor_sync(0xffffffffu, L, o);
    const int warp = threadIdx.x >> 5, lane = threadIdx.x & 31;
    if (lane == 0) rs[warp] = L;
    __syncthreads();
    if (threadIdx.x == 0) {
        float t = 0.0f;
        #pragma unroll
        for (int w = 0; w < 8; w++) t += rs[w];
        atomicAdd(out, t);
    }
}

// ---------------------------------------------------------------------------
extern "C" void kernel_launch(void* const* d_in, const int* in_sizes, int n_in,
                              void* d_out, int out_size) {
    const float* v  = (const float*)d_in[0];   // [NM, D] fp32
    const float* wp = (const float*)d_in[1];   // scalar w
    // d_in[2] = b (cancels analytically), d_in[3] = speakers (compile-time)
    float* out = (float*)d_out;

    init_kernel<<<(NM + 255) / 256, 256>>>(out);
    prep_kernel<<<N_SPK, 256>>>(v);
    dim3 grid(NM / 128, N_SPK / 128);          // 256 x 16 = 4096 CTAs
    gemm_lse_kernel<<<grid, 256>>>(wp);
    loss_kernel<<<NM / 256, 256>>>(wp, out);
}

// round 3
// speedup vs baseline: 1.6503x; 1.6503x over previous
#include <cuda_runtime.h>
#include <math.h>

#define N_SPK 2048
#define M_UTT 16
#define D_EMB 512
#define NM (N_SPK * M_UTT)
#define EPSF 1e-8f

// Scratch (allocation-free rule: __device__ globals)
__device__ float g_Cn[N_SPK * D_EMB];     // normalized centroids  [2048,512]
__device__ float g_vn[NM * D_EMB];        // normalized utterances [32768,512]
__device__ float g_sdiag[NM];             // cos(C_min[j], v_j)
__device__ float g_sself[NM];             // cos(C[spk(j)], v_j)  (as GEMM would compute it)
__device__ float g_colsum[NM];            // sum_n exp(w*(S[n,j]-1)) with full-C diag row

// ---------------------------------------------------------------------------
// Init: zero colsum + output (d_out is poisoned before timing; replays must re-zero)
// ---------------------------------------------------------------------------
__global__ void init_kernel(float* out) {
    int i = blockIdx.x * blockDim.x + threadIdx.x;
    if (i < NM) g_colsum[i] = 0.0f;
    if (i == 0) *out = 0.0f;
}

// ---------------------------------------------------------------------------
// Prep: one block per speaker. Computes Cn, vn, S_diag, S_self.
//   sq[m]  = ||v_m||^2
//   dsv[m] = ssum . v_m
//   ss     = ||ssum||^2
//   cm = ssum - v_m:  cm.v = dsv - sq ;  ||cm||^2 = ss - 2 dsv + sq
// ---------------------------------------------------------------------------
__global__ __launch_bounds__(256) void prep_kernel(const float* __restrict__ v) {
    __shared__ float sv[M_UTT * D_EMB];     // 32 KB
    __shared__ float red[8][33];
    __shared__ float fin[33];

    const int tid = threadIdx.x;
    const int n = blockIdx.x;

    // Load this speaker's 16x512 block
    {
        const float4* src = (const float4*)(v + (size_t)n * M_UTT * D_EMB);
        float4* dst = (float4*)sv;
        #pragma unroll
        for (int i = 0; i < (M_UTT * D_EMB / 4) / 256; i++)
            dst[tid + i * 256] = src[tid + i * 256];
    }
    __syncthreads();

    // Thread owns columns d0 = tid, d1 = tid + 256
    float s0 = 0.0f, s1 = 0.0f;
    #pragma unroll
    for (int m = 0; m < M_UTT; m++) {
        s0 += sv[m * D_EMB + tid];
        s1 += sv[m * D_EMB + tid + 256];
    }

    float vals[33];
    #pragma unroll
    for (int m = 0; m < M_UTT; m++) {
        float x0 = sv[m * D_EMB + tid];
        float x1 = sv[m * D_EMB + tid + 256];
        vals[m]      = x0 * x0 + x1 * x1;   // sq partial
        vals[16 + m] = s0 * x0 + s1 * x1;   // dsv partial
    }
    vals[32] = s0 * s0 + s1 * s1;           // ss partial

    // Block reduction of 33 values
    #pragma unroll
    for (int i = 0; i < 33; i++) {
        float x = vals[i];
        #pragma unroll
        for (int o = 16; o > 0; o >>= 1)
            x += __shfl_xor_sync(0xffffffffu, x, o);
        vals[i] = x;
    }
    const int warp = tid >> 5, lane = tid & 31;
    if (lane == 0) {
        #pragma unroll
        for (int i = 0; i < 33; i++) red[warp][i] = vals[i];
    }
    __syncthreads();
    if (tid < 33) {
        float x = 0.0f;
        #pragma unroll
        for (int w = 0; w < 8; w++) x += red[w][tid];
        fin[tid] = x;
    }
    __syncthreads();

    const float ss = fin[32];
    const float rn = sqrtf(ss);
    const float cinv = 1.0f / fmaxf(rn, (float)M_UTT * EPSF);   // normalize(ssum/M) == ssum / max(rn, M*eps)

    g_Cn[n * D_EMB + tid]       = s0 * cinv;
    g_Cn[n * D_EMB + tid + 256] = s1 * cinv;

    #pragma unroll
    for (int m = 0; m < M_UTT; m++) {
        float rv = 1.0f / fmaxf(sqrtf(fin[m]), EPSF);
        size_t base = (size_t)(n * M_UTT + m) * D_EMB;
        g_vn[base + tid]       = sv[m * D_EMB + tid] * rv;
        g_vn[base + tid + 256] = sv[m * D_EMB + tid + 256] * rv;
    }

    if (tid < M_UTT) {
        const int m = tid;
        float sq  = fin[m];
        float dsv = fin[16 + m];
        float nv  = fmaxf(sqrtf(sq), EPSF);
        float cm2 = fmaxf(ss - 2.0f * dsv + sq, 0.0f);
        const float invMm1 = 1.0f / (float)(M_UTT - 1);
        float ncm = fmaxf(sqrtf(cm2) * invMm1, EPSF);
        float sd  = ((dsv - sq) * invMm1) / (ncm * nv);
        // exactly the value the uniform GEMM produces for row spk(j), col j:
        float sf  = (dsv * cinv) / nv;
        g_sdiag[n * M_UTT + m] = sd;
        g_sself[n * M_UTT + m] = sf;
    }
}

// ---------------------------------------------------------------------------
// Fused GEMM + exp epilogue.
// S = Cn @ vn^T, tiles 128x128, threads 256 (16x16 grid of 8x8 micro-tiles).
// colsum[j] += sum_rows exp(w * (S - 1))   [shift by max logit w*1+b -> b cancels]
// ---------------------------------------------------------------------------
__global__ __launch_bounds__(256, 2) void gemm_lse_kernel(const float* __restrict__ wp) {
    __shared__ float As[8][128];
    __shared__ float Bs[8][128];
    __shared__ float csh[128];

    const int tid = threadIdx.x;
    const int rowBase = blockIdx.y * 128;
    const int colBase = blockIdx.x * 128;
    const int tx = tid & 15;          // column group
    const int ty = tid >> 4;          // row group
    const int lr = tid >> 1;          // 0..127: tile row loaded by this thread
    const int lk = (tid & 1) * 4;     // k sub-offset 0 or 4

    const float* Ap = g_Cn + (size_t)(rowBase + lr) * D_EMB + lk;
    const float* Bp = g_vn + (size_t)(colBase + lr) * D_EMB + lk;

    float acc[8][8];
    #pragma unroll
    for (int i = 0; i < 8; i++)
        #pragma unroll
        for (int j = 0; j < 8; j++) acc[i][j] = 0.0f;

    float4 a4 = *(const float4*)Ap;
    float4 b4 = *(const float4*)Bp;

    for (int kt = 8; kt <= D_EMB; kt += 8) {
        __syncthreads();
        As[lk + 0][lr] = a4.x; As[lk + 1][lr] = a4.y;
        As[lk + 2][lr] = a4.z; As[lk + 3][lr] = a4.w;
        Bs[lk + 0][lr] = b4.x; Bs[lk + 1][lr] = b4.y;
        Bs[lk + 2][lr] = b4.z; Bs[lk + 3][lr] = b4.w;
        __syncthreads();
        if (kt < D_EMB) {                 // prefetch next tile into registers
            a4 = *(const float4*)(Ap + kt);
            b4 = *(const float4*)(Bp + kt);
        }
        #pragma unroll
        for (int k = 0; k < 8; k++) {
            float a[8], b[8];
            *(float4*)(a)     = *(const float4*)&As[k][ty * 8];
            *(float4*)(a + 4) = *(const float4*)&As[k][ty * 8 + 4];
            *(float4*)(b)     = *(const float4*)&Bs[k][tx * 8];
            *(float4*)(b + 4) = *(const float4*)&Bs[k][tx * 8 + 4];
            #pragma unroll
            for (int i = 0; i < 8; i++)
                #pragma unroll
                for (int j = 0; j < 8; j++)
                    acc[i][j] += a[i] * b[j];
        }
    }

    // Epilogue: per-column sum of exp(w*(S-1)) over this tile's 128 rows
    if (tid < 128) csh[tid] = 0.0f;
    const float wv = *wp;
    __syncthreads();
    #pragma unroll
    for (int j = 0; j < 8; j++) {
        float s = 0.0f;
        #pragma unroll
        for (int i = 0; i < 8; i++)
            s += __expf(wv * (acc[i][j] - 1.0f));
        atomicAdd(&csh[tx * 8 + j], s);
    }
    __syncthreads();
    if (tid < 128) atomicAdd(&g_colsum[colBase + tid], csh[tid]);
}

// ---------------------------------------------------------------------------
// Final loss:
//   csum_j = colsum_j - exp(w*(S_self-1)) + exp(w*(S_diag-1))
//   L_j    = w*(1 - S_diag_j) + log(csum_j)        (b cancels)
// ---------------------------------------------------------------------------
__global__ __launch_bounds__(256) void loss_kernel(const float* __restrict__ wp,
                                                   float* __restrict__ out) {
    __shared__ float rs[8];
    const int j = blockIdx.x * blockDim.x + threadIdx.x;
    const float wv = *wp;
    float L = 0.0f;
    if (j < NM) {
        float sd = g_sdiag[j];
        float sf = g_sself[j];
        float cs = g_colsum[j] - __expf(wv * (sf - 1.0f)) + __expf(wv * (sd - 1.0f));
        L = wv * (1.0f - sd) + logf(cs);
    }
    #pragma unroll
    for (int o = 16; o > 0; o >>= 1)
        L += __shfl_xor_sync(0xffffffffu, L, o);
    const int warp = threadIdx.x >> 5, lane = threadIdx.x & 31;
    if (lane == 0) rs[warp] = L;
    __syncthreads();
    if (threadIdx.x == 0) {
        float t = 0.0f;
        #pragma unroll
        for (int w = 0; w < 8; w++) t += rs[w];
        atomicAdd(out, t);
    }
}

// ---------------------------------------------------------------------------
extern "C" void kernel_launch(void* const* d_in, const int* in_sizes, int n_in,
                              void* d_out, int out_size) {
    const float* v  = (const float*)d_in[0];   // [NM, D] fp32
    const float* wp = (const float*)d_in[1];   // scalar w
    // d_in[2] = b (cancels analytically), d_in[3] = speakers (compile-time)
    float* out = (float*)d_out;

    init_kernel<<<(NM + 255) / 256, 256>>>(out);
    prep_kernel<<<N_SPK, 256>>>(v);
    dim3 grid(NM / 128, N_SPK / 128);          // 256 x 16 = 4096 CTAs
    gemm_lse_kernel<<<grid, 256>>>(wp);
    loss_kernel<<<NM / 256, 256>>>(wp, out);
}

// round 5
// speedup vs baseline: 9.2361x; 5.5966x over previous
#include <cuda_runtime.h>
#include <cuda_bf16.h>
#include <cstdint>
#include <math.h>

#define N_SPK 2048
#define M_UTT 16
#define D_EMB 512
#define NM (N_SPK * M_UTT)
#define EPSF 1e-8f

// ---------------- scratch (allocation-free rule: __device__ globals) -------
__device__ __nv_bfloat16 g_vnb[NM * D_EMB];     // normalized utterances, bf16
__device__ __nv_bfloat16 g_Cnb[N_SPK * D_EMB];  // normalized centroids,  bf16
__device__ float g_sdiag[NM];                   // cos(C_min[j], v_j) fp32-exact
__device__ float g_sself[NM];                   // dot of bf16-rounded Cn,vn
__device__ float g_colsum[NM];                  // sum_n exp(w*(S[n,j]-1))

// ---------------- helpers ---------------------------------------------------
__device__ __forceinline__ uint32_t smem_u32(const void* p) {
    uint32_t a;
    asm("{ .reg .u64 t; cvta.to.shared.u64 t, %1; cvt.u32.u64 %0, t; }" : "=r"(a) : "l"(p));
    return a;
}
__device__ __forceinline__ void cp16(uint32_t s, const void* g) {
    asm volatile("cp.async.cg.shared.global [%0], [%1], 16;" :: "r"(s), "l"(g) : "memory");
}
__device__ __forceinline__ void cp_commit() { asm volatile("cp.async.commit_group;" ::: "memory"); }
__device__ __forceinline__ void cp_wait1()  { asm volatile("cp.async.wait_group 1;" ::: "memory"); }
__device__ __forceinline__ float ex2a(float x) {
    float r; asm("ex2.approx.f32 %0, %1;" : "=f"(r) : "f"(x)); return r;
}
#define MMA_BF16(d, a0, a1, a2, a3, b0, b1)                                   \
    asm volatile(                                                             \
        "mma.sync.aligned.m16n8k16.row.col.f32.bf16.bf16.f32 "                \
        "{%0,%1,%2,%3}, {%4,%5,%6,%7}, {%8,%9}, {%0,%1,%2,%3};"               \
        : "+f"(d[0]), "+f"(d[1]), "+f"(d[2]), "+f"(d[3])                      \
        : "r"(a0), "r"(a1), "r"(a2), "r"(a3), "r"(b0), "r"(b1))

// ---------------- init ------------------------------------------------------
__global__ void init_kernel(float* out) {
    if (blockIdx.x == 0 && threadIdx.x == 0) *out = 0.0f;
}

// ---------------- prep: per-speaker normalize + diag terms -----------------
__global__ __launch_bounds__(256) void prep_kernel(const float* __restrict__ v) {
    __shared__ float sv[M_UTT * D_EMB];
    __shared__ float red[8][33];
    __shared__ float fin[33];

    const int tid = threadIdx.x;
    const int n = blockIdx.x;

    {
        const float4* src = (const float4*)(v + (size_t)n * M_UTT * D_EMB);
        float4* dst = (float4*)sv;
        #pragma unroll
        for (int i = 0; i < (M_UTT * D_EMB / 4) / 256; i++)
            dst[tid + i * 256] = src[tid + i * 256];
    }
    __syncthreads();

    float s0 = 0.0f, s1 = 0.0f;
    #pragma unroll
    for (int m = 0; m < M_UTT; m++) {
        s0 += sv[m * D_EMB + tid];
        s1 += sv[m * D_EMB + tid + 256];
    }

    float vals[33];
    #pragma unroll
    for (int m = 0; m < M_UTT; m++) {
        float x0 = sv[m * D_EMB + tid];
        float x1 = sv[m * D_EMB + tid + 256];
        vals[m]      = x0 * x0 + x1 * x1;
        vals[16 + m] = s0 * x0 + s1 * x1;
    }
    vals[32] = s0 * s0 + s1 * s1;

    #pragma unroll
    for (int i = 0; i < 33; i++) {
        float x = vals[i];
        #pragma unroll
        for (int o = 16; o > 0; o >>= 1) x += __shfl_xor_sync(0xffffffffu, x, o);
        vals[i] = x;
    }
    const int warp = tid >> 5, lane = tid & 31;
    if (lane == 0) {
        #pragma unroll
        for (int i = 0; i < 33; i++) red[warp][i] = vals[i];
    }
    __syncthreads();
    if (tid < 33) {
        float x = 0.0f;
        #pragma unroll
        for (int w = 0; w < 8; w++) x += red[w][tid];
        fin[tid] = x;
    }
    __syncthreads();

    const float ss = fin[32];
    const float cinv = 1.0f / fmaxf(sqrtf(ss), (float)M_UTT * EPSF);

    __nv_bfloat16 cb0 = __float2bfloat16(s0 * cinv);
    __nv_bfloat16 cb1 = __float2bfloat16(s1 * cinv);
    g_Cnb[n * D_EMB + tid]       = cb0;
    g_Cnb[n * D_EMB + tid + 256] = cb1;
    const float fc0 = __bfloat162float(cb0);
    const float fc1 = __bfloat162float(cb1);

    float sfp[16];
    #pragma unroll
    for (int m = 0; m < M_UTT; m++) {
        float rv = 1.0f / fmaxf(sqrtf(fin[m]), EPSF);
        __nv_bfloat16 vb0 = __float2bfloat16(sv[m * D_EMB + tid] * rv);
        __nv_bfloat16 vb1 = __float2bfloat16(sv[m * D_EMB + tid + 256] * rv);
        size_t base = (size_t)(n * M_UTT + m) * D_EMB;
        g_vnb[base + tid]       = vb0;
        g_vnb[base + tid + 256] = vb1;
        sfp[m] = fc0 * __bfloat162float(vb0) + fc1 * __bfloat162float(vb1);
    }

    #pragma unroll
    for (int m = 0; m < 16; m++) {
        float x = sfp[m];
        #pragma unroll
        for (int o = 16; o > 0; o >>= 1) x += __shfl_xor_sync(0xffffffffu, x, o);
        sfp[m] = x;
    }
    if (lane == 0) {
        #pragma unroll
        for (int m = 0; m < 16; m++) red[warp][m] = sfp[m];
    }
    __syncthreads();
    if (tid < 16) {
        float x = 0.0f;
        #pragma unroll
        for (int w = 0; w < 8; w++) x += red[w][tid];
        g_sself[n * M_UTT + tid] = x;

        float sq  = fin[tid];
        float dsv = fin[16 + tid];
        float nv  = fmaxf(sqrtf(sq), EPSF);
        float cm2 = fmaxf(ss - 2.0f * dsv + sq, 0.0f);
        const float invMm1 = 1.0f / (float)(M_UTT - 1);
        float ncm = fmaxf(sqrtf(cm2) * invMm1, EPSF);
        g_sdiag[n * M_UTT + tid] = ((dsv - sq) * invMm1) / (ncm * nv);
    }
}

// ---------------- mma.sync GEMM + fused exp rowsum --------------------------
// S[u,s] = vn[u,:] . Cn[s,:]; A tile (M=128, K=512) resident; B (Cn) streamed
// in BK=64 double-buffered chunks over 16 N-tiles of 128. Rowsum of
// exp(w*(S-1)) accumulates in registers; plain store (CTA owns its 128 rows).
#define A_PITCH 520                    // elements (pad 8): conflict-free frags
#define B_PITCH 72                     // elements (pad 8)
#define SA_BYTES (128 * A_PITCH * 2)   // 133120
#define SB_BYTES (128 * B_PITCH * 2)   // 18432 per buffer
#define SB_OFF  SA_BYTES
#define SRED_OFF (SB_OFF + 2 * SB_BYTES)
#define SMEM_SZ (SRED_OFF + 256 * 4)

__global__ __launch_bounds__(256, 1) void gemm_lse_kernel(const float* __restrict__ wp) {
    extern __shared__ char smem[];
    const uint32_t sbase = smem_u32(smem);
    const uint32_t* As32 = (const uint32_t*)smem;
    float* red = (float*)(smem + SRED_OFF);

    const int tid = threadIdx.x;
    const int lane = tid & 31, wid = tid >> 5;
    const int warpM = wid >> 1, warpN = wid & 1;
    const int g = lane >> 2, t = lane & 3;
    const int uttBase = blockIdx.x * 128;

    // ---- stage A (128 x 512 bf16 -> padded rows), group 0 with B chunk 0 --
    {
        const __nv_bfloat16* vsrc = g_vnb + (size_t)uttBase * D_EMB;
        #pragma unroll 8
        for (int i = 0; i < 32; i++) {
            int flat = tid + 256 * i;          // 0..8191
            int row = flat >> 6, cc = flat & 63;
            cp16(sbase + row * (A_PITCH * 2) + cc * 16,
                 vsrc + (size_t)row * D_EMB + cc * 8);
        }
    }
    // B chunk c -> buffer buf
    auto loadB = [&](int c, int buf) {
        const int ntile = c >> 3, kc = c & 7;
        const __nv_bfloat16* bsrc = g_Cnb + (size_t)(ntile * 128) * D_EMB + kc * 64;
        const uint32_t bb = sbase + SB_OFF + buf * SB_BYTES;
        #pragma unroll
        for (int i = 0; i < 4; i++) {
            int flat = tid + 256 * i;          // 0..1023
            int row = flat >> 3, k8 = flat & 7;
            cp16(bb + row * (B_PITCH * 2) + k8 * 16,
                 bsrc + (size_t)row * D_EMB + k8 * 8);
        }
    };
    loadB(0, 0); cp_commit();
    loadB(1, 1); cp_commit();

    const float wv = *wp;
    const float c1 = wv * 1.44269504f;         // w * log2(e)
    const float c0 = -c1;

    float acc[2][8][4];
    #pragma unroll
    for (int i = 0; i < 2; i++)
        #pragma unroll
        for (int j = 0; j < 8; j++)
            #pragma unroll
            for (int r = 0; r < 4; r++) acc[i][j][r] = 0.0f;
    float rs[2][2] = {{0.0f, 0.0f}, {0.0f, 0.0f}};

    #pragma unroll 1
    for (int c = 0; c < 128; c++) {
        const int buf = c & 1;
        cp_wait1();
        __syncthreads();

        const uint32_t* B32 = (const uint32_t*)(smem + SB_OFF + buf * SB_BYTES);
        // A word base for this chunk's K window: kc*64 elements = kc*32 words
        const int kcw = (c & 7) * 32;

        #pragma unroll
        for (int s = 0; s < 4; s++) {
            uint32_t ra[2][4];
            #pragma unroll
            for (int i = 0; i < 2; i++) {
                const int arow = warpM * 32 + i * 16 + g;
                const int wi = arow * (A_PITCH / 2) + kcw + s * 8 + t;
                ra[i][0] = As32[wi];
                ra[i][1] = As32[wi + 8 * (A_PITCH / 2)];
                ra[i][2] = As32[wi + 4];
                ra[i][3] = As32[wi + 8 * (A_PITCH / 2) + 4];
            }
            #pragma unroll
            for (int j = 0; j < 8; j++) {
                const int nrow = warpN * 64 + j * 8 + g;
                const int wi = nrow * (B_PITCH / 2) + s * 8 + t;
                const uint32_t rb0 = B32[wi];
                const uint32_t rb1 = B32[wi + 4];
                MMA_BF16(acc[0][j], ra[0][0], ra[0][1], ra[0][2], ra[0][3], rb0, rb1);
                MMA_BF16(acc[1][j], ra[1][0], ra[1][1], ra[1][2], ra[1][3], rb0, rb1);
            }
        }

        __syncthreads();                        // all warps done reading buf
        if (c + 2 < 128) loadB(c + 2, buf);
        cp_commit();                            // one group per iteration

        if ((c & 7) == 7) {                     // N-tile done: exp into rowsums
            #pragma unroll
            for (int i = 0; i < 2; i++) {
                float a0 = 0.0f, a1 = 0.0f;
                #pragma unroll
                for (int j = 0; j < 8; j++) {
                    a0 += ex2a(fmaf(acc[i][j][0], c1, c0)) + ex2a(fmaf(acc[i][j][1], c1, c0));
                    a1 += ex2a(fmaf(acc[i][j][2], c1, c0)) + ex2a(fmaf(acc[i][j][3], c1, c0));
                    acc[i][j][0] = acc[i][j][1] = acc[i][j][2] = acc[i][j][3] = 0.0f;
                }
                rs[i][0] += a0;
                rs[i][1] += a1;
            }
        }
    }

    // ---- reduce rowsums over the quad (t = lane&3 spans n-columns) --------
    #pragma unroll
    for (int i = 0; i < 2; i++)
        #pragma unroll
        for (int r = 0; r < 2; r++) {
            float x = rs[i][r];
            x += __shfl_xor_sync(0xffffffffu, x, 1);
            x += __shfl_xor_sync(0xffffffffu, x, 2);
            rs[i][r] = x;
        }
    if (t == 0) {
        #pragma unroll
        for (int i = 0; i < 2; i++)
            #pragma unroll
            for (int r = 0; r < 2; r++)
                red[warpN * 128 + warpM * 32 + i * 16 + r * 8 + g] = rs[i][r];
    }
    __syncthreads();
    if (tid < 128)
        g_colsum[uttBase + tid] = red[tid] + red[128 + tid];
}

// ---------------- final loss ------------------------------------------------
__global__ __launch_bounds__(256) void loss_kernel(const float* __restrict__ wp,
                                                   float* __restrict__ out) {
    __shared__ float rsm[8];
    const int j = blockIdx.x * blockDim.x + threadIdx.x;
    const float wv = *wp;
    const float c1 = wv * 1.44269504f;
    const float c0 = -c1;
    float L = 0.0f;
    if (j < NM) {
        float sd = g_sdiag[j];
        float sf = g_sself[j];
        float cs = g_colsum[j] - ex2a(fmaf(sf, c1, c0)) + ex2a(fmaf(sd, c1, c0));
        L = wv * (1.0f - sd) + logf(cs);
    }
    #pragma unroll
    for (int o = 16; o > 0; o >>= 1) L += __shfl_xor_sync(0xffffffffu, L, o);
    const int warp = threadIdx.x >> 5, lane = threadIdx.x & 31;
    if (lane == 0) rsm[warp] = L;
    __syncthreads();
    if (threadIdx.x == 0) {
        float tacc = 0.0f;
        #pragma unroll
        for (int w = 0; w < 8; w++) tacc += rsm[w];
        atomicAdd(out, tacc);
    }
}

// ---------------------------------------------------------------------------
extern "C" void kernel_launch(void* const* d_in, const int* in_sizes, int n_in,
                              void* d_out, int out_size) {
    const float* v  = (const float*)d_in[0];   // [NM, D] fp32
    const float* wp = (const float*)d_in[1];   // scalar w (b cancels analytically)
    float* out = (float*)d_out;

    cudaFuncSetAttribute(gemm_lse_kernel,
                         cudaFuncAttributeMaxDynamicSharedMemorySize, SMEM_SZ);

    init_kernel<<<1, 32>>>(out);
    prep_kernel<<<N_SPK, 256>>>(v);
    gemm_lse_kernel<<<NM / 128, 256, SMEM_SZ>>>(wp);
    loss_kernel<<<NM / 256, 256>>>(wp, out);
}

// round 6
// speedup vs baseline: 9.7386x; 1.0544x over previous
#include <cuda_runtime.h>
#include <cuda_bf16.h>
#include <cstdint>
#include <math.h>

#define N_SPK 2048
#define M_UTT 16
#define D_EMB 512
#define NM (N_SPK * M_UTT)
#define EPSF 1e-8f

// ---------------- scratch (allocation-free rule: __device__ globals) -------
__device__ __nv_bfloat16 g_vnb[NM * D_EMB];     // normalized utterances, bf16
__device__ __nv_bfloat16 g_Cnb[N_SPK * D_EMB];  // normalized centroids,  bf16
__device__ float g_sdiag[NM];                   // cos(C_min[j], v_j) fp32-exact
__device__ float g_sself[NM];                   // dot of bf16-rounded Cn,vn
__device__ float g_colsum[NM];                  // sum_n exp(w*(S[n,j]-1))

// ---------------- helpers ---------------------------------------------------
__device__ __forceinline__ uint32_t smem_u32(const void* p) {
    uint32_t a;
    asm("{ .reg .u64 t; cvta.to.shared.u64 t, %1; cvt.u32.u64 %0, t; }" : "=r"(a) : "l"(p));
    return a;
}
__device__ __forceinline__ void cp16(uint32_t s, const void* g) {
    asm volatile("cp.async.cg.shared.global [%0], [%1], 16;" :: "r"(s), "l"(g) : "memory");
}
__device__ __forceinline__ void cp_commit() { asm volatile("cp.async.commit_group;" ::: "memory"); }
__device__ __forceinline__ void cp_wait1()  { asm volatile("cp.async.wait_group 1;" ::: "memory"); }
__device__ __forceinline__ float ex2a(float x) {
    float r; asm("ex2.approx.f32 %0, %1;" : "=f"(r) : "f"(x)); return r;
}
#define MMA_BF16(d, a0, a1, a2, a3, b0, b1)                                   \
    asm volatile(                                                             \
        "mma.sync.aligned.m16n8k16.row.col.f32.bf16.bf16.f32 "                \
        "{%0,%1,%2,%3}, {%4,%5,%6,%7}, {%8,%9}, {%0,%1,%2,%3};"               \
        : "+f"(d[0]), "+f"(d[1]), "+f"(d[2]), "+f"(d[3])                      \
        : "r"(a0), "r"(a1), "r"(a2), "r"(a3), "r"(b0), "r"(b1))

// ---------------- init ------------------------------------------------------
__global__ void init_kernel(float* out) {
    if (blockIdx.x == 0 && threadIdx.x == 0) *out = 0.0f;
}

// ---------------- prep: per-speaker normalize + diag terms -----------------
__global__ __launch_bounds__(256) void prep_kernel(const float* __restrict__ v) {
    __shared__ float sv[M_UTT * D_EMB];
    __shared__ float red[8][33];
    __shared__ float fin[33];

    const int tid = threadIdx.x;
    const int n = blockIdx.x;

    {
        const float4* src = (const float4*)(v + (size_t)n * M_UTT * D_EMB);
        float4* dst = (float4*)sv;
        #pragma unroll
        for (int i = 0; i < (M_UTT * D_EMB / 4) / 256; i++)
            dst[tid + i * 256] = src[tid + i * 256];
    }
    __syncthreads();

    float s0 = 0.0f, s1 = 0.0f;
    #pragma unroll
    for (int m = 0; m < M_UTT; m++) {
        s0 += sv[m * D_EMB + tid];
        s1 += sv[m * D_EMB + tid + 256];
    }

    float vals[33];
    #pragma unroll
    for (int m = 0; m < M_UTT; m++) {
        float x0 = sv[m * D_EMB + tid];
        float x1 = sv[m * D_EMB + tid + 256];
        vals[m]      = x0 * x0 + x1 * x1;
        vals[16 + m] = s0 * x0 + s1 * x1;
    }
    vals[32] = s0 * s0 + s1 * s1;

    #pragma unroll
    for (int i = 0; i < 33; i++) {
        float x = vals[i];
        #pragma unroll
        for (int o = 16; o > 0; o >>= 1) x += __shfl_xor_sync(0xffffffffu, x, o);
        vals[i] = x;
    }
    const int warp = tid >> 5, lane = tid & 31;
    if (lane == 0) {
        #pragma unroll
        for (int i = 0; i < 33; i++) red[warp][i] = vals[i];
    }
    __syncthreads();
    if (tid < 33) {
        float x = 0.0f;
        #pragma unroll
        for (int w = 0; w < 8; w++) x += red[w][tid];
        fin[tid] = x;
    }
    __syncthreads();

    const float ss = fin[32];
    const float cinv = 1.0f / fmaxf(sqrtf(ss), (float)M_UTT * EPSF);

    __nv_bfloat16 cb0 = __float2bfloat16(s0 * cinv);
    __nv_bfloat16 cb1 = __float2bfloat16(s1 * cinv);
    g_Cnb[n * D_EMB + tid]       = cb0;
    g_Cnb[n * D_EMB + tid + 256] = cb1;
    const float fc0 = __bfloat162float(cb0);
    const float fc1 = __bfloat162float(cb1);

    float sfp[16];
    #pragma unroll
    for (int m = 0; m < M_UTT; m++) {
        float rv = 1.0f / fmaxf(sqrtf(fin[m]), EPSF);
        __nv_bfloat16 vb0 = __float2bfloat16(sv[m * D_EMB + tid] * rv);
        __nv_bfloat16 vb1 = __float2bfloat16(sv[m * D_EMB + tid + 256] * rv);
        size_t base = (size_t)(n * M_UTT + m) * D_EMB;
        g_vnb[base + tid]       = vb0;
        g_vnb[base + tid + 256] = vb1;
        sfp[m] = fc0 * __bfloat162float(vb0) + fc1 * __bfloat162float(vb1);
    }

    #pragma unroll
    for (int m = 0; m < 16; m++) {
        float x = sfp[m];
        #pragma unroll
        for (int o = 16; o > 0; o >>= 1) x += __shfl_xor_sync(0xffffffffu, x, o);
        sfp[m] = x;
    }
    if (lane == 0) {
        #pragma unroll
        for (int m = 0; m < 16; m++) red[warp][m] = sfp[m];
    }
    __syncthreads();
    if (tid < 16) {
        float x = 0.0f;
        #pragma unroll
        for (int w = 0; w < 8; w++) x += red[w][tid];
        g_sself[n * M_UTT + tid] = x;

        float sq  = fin[tid];
        float dsv = fin[16 + tid];
        float nv  = fmaxf(sqrtf(sq), EPSF);
        float cm2 = fmaxf(ss - 2.0f * dsv + sq, 0.0f);
        const float invMm1 = 1.0f / (float)(M_UTT - 1);
        float ncm = fmaxf(sqrtf(cm2) * invMm1, EPSF);
        g_sdiag[n * M_UTT + tid] = ((dsv - sq) * invMm1) / (ncm * nv);
    }
}

// ---------------- mma.sync GEMM + fused exp rowsum --------------------------
// S[u,s] = vn[u,:] . Cn[s,:]; A tile (M=128, K=512) resident; B (Cn) streamed
// in BK=64 chunks of 256 speakers. Warp tile m64 x n64 (128 accs/thread);
// CTA = 2(M) x 4(N) warps = 128 x 256. 8 N-tiles x 8 K-chunks = 64 iters.
#define A_PITCH 520                    // bf16 elements (pad 8), 260 words
#define B_PITCH 72                     // bf16 elements (pad 8), 36 words
#define SA_BYTES (128 * A_PITCH * 2)   // 133120
#define SB_BYTES (256 * B_PITCH * 2)   // 36864 per buffer
#define SB_OFF   SA_BYTES
#define SRED_OFF (SB_OFF + 2 * SB_BYTES)   // 206848
#define SMEM_SZ  (SRED_OFF + 4 * 128 * 4)  // 208896

__global__ __launch_bounds__(256, 1) void gemm_lse_kernel(const float* __restrict__ wp) {
    extern __shared__ char smem[];
    const uint32_t sbase = smem_u32(smem);
    const uint32_t* As32 = (const uint32_t*)smem;
    float* red = (float*)(smem + SRED_OFF);

    const int tid = threadIdx.x;
    const int lane = tid & 31, wid = tid >> 5;
    const int warpM = wid & 1;            // 2 warps over M=128
    const int warpN = wid >> 1;           // 4 warps over N=256
    const int g = lane >> 2, t = lane & 3;
    const int uttBase = blockIdx.x * 128;

    // ---- stage A (128 x 512 bf16, padded rows); group 0 with B chunk 0 ----
    {
        const __nv_bfloat16* vsrc = g_vnb + (size_t)uttBase * D_EMB;
        #pragma unroll 8
        for (int i = 0; i < 32; i++) {
            int flat = tid + 256 * i;          // 0..8191
            int row = flat >> 6, cc = flat & 63;
            cp16(sbase + row * (A_PITCH * 2) + cc * 16,
                 vsrc + (size_t)row * D_EMB + cc * 8);
        }
    }
    // B chunk c (ntile = c>>3 covers 256 speakers, kc = c&7 covers k64)
    auto loadB = [&](int c, int buf) {
        const int ntile = c >> 3, kc = c & 7;
        const __nv_bfloat16* bsrc = g_Cnb + (size_t)(ntile * 256) * D_EMB + kc * 64;
        const uint32_t bb = sbase + SB_OFF + buf * SB_BYTES;
        #pragma unroll
        for (int i = 0; i < 8; i++) {
            int flat = tid + 256 * i;          // 0..2047
            int row = flat >> 3, k8 = flat & 7;
            cp16(bb + row * (B_PITCH * 2) + k8 * 16,
                 bsrc + (size_t)row * D_EMB + k8 * 8);
        }
    };
    loadB(0, 0); cp_commit();
    loadB(1, 1); cp_commit();

    const float wv = *wp;
    const float c1 = wv * 1.44269504f;         // w * log2(e)
    const float c0 = -c1;

    float acc[4][8][4];                        // 128 accumulators
    #pragma unroll
    for (int i = 0; i < 4; i++)
        #pragma unroll
        for (int j = 0; j < 8; j++)
            #pragma unroll
            for (int r = 0; r < 4; r++) acc[i][j][r] = 0.0f;
    float rs[4][2] = {{0,0},{0,0},{0,0},{0,0}};

    #pragma unroll 1
    for (int c = 0; c < 64; c++) {
        const int buf = c & 1;
        cp_wait1();
        __syncthreads();

        const uint32_t* B32 = (const uint32_t*)(smem + SB_OFF + buf * SB_BYTES);
        const int kcw = (c & 7) * 32;          // k-chunk word base in A rows

        #pragma unroll
        for (int s = 0; s < 4; s++) {
            uint32_t ra[4][4];
            #pragma unroll
            for (int i = 0; i < 4; i++) {
                const int arow = warpM * 64 + i * 16 + g;
                const int wi = arow * (A_PITCH / 2) + kcw + s * 8 + t;
                ra[i][0] = As32[wi];
                ra[i][1] = As32[wi + 8 * (A_PITCH / 2)];
                ra[i][2] = As32[wi + 4];
                ra[i][3] = As32[wi + 8 * (A_PITCH / 2) + 4];
            }
            #pragma unroll
            for (int j = 0; j < 8; j++) {
                const int nrow = warpN * 64 + j * 8 + g;
                const int wi = nrow * (B_PITCH / 2) + s * 8 + t;
                const uint32_t rb0 = B32[wi];
                const uint32_t rb1 = B32[wi + 4];
                #pragma unroll
                for (int i = 0; i < 4; i++)
                    MMA_BF16(acc[i][j], ra[i][0], ra[i][1], ra[i][2], ra[i][3], rb0, rb1);
            }
        }

        __syncthreads();                       // all warps done reading buf
        if (c + 2 < 64) loadB(c + 2, buf);
        cp_commit();                           // one group per iteration

        if ((c & 7) == 7) {                    // N-tile done: exp into rowsums
            #pragma unroll
            for (int i = 0; i < 4; i++) {
                float a0 = 0.0f, a1 = 0.0f;
                #pragma unroll
                for (int j = 0; j < 8; j++) {
                    a0 += ex2a(fmaf(acc[i][j][0], c1, c0)) + ex2a(fmaf(acc[i][j][1], c1, c0));
                    a1 += ex2a(fmaf(acc[i][j][2], c1, c0)) + ex2a(fmaf(acc[i][j][3], c1, c0));
                    acc[i][j][0] = acc[i][j][1] = acc[i][j][2] = acc[i][j][3] = 0.0f;
                }
                rs[i][0] += a0;
                rs[i][1] += a1;
            }
        }
    }

    // ---- reduce rowsums: quad (t spans n-pairs) then across warpN ---------
    #pragma unroll
    for (int i = 0; i < 4; i++)
        #pragma unroll
        for (int r = 0; r < 2; r++) {
            float x = rs[i][r];
            x += __shfl_xor_sync(0xffffffffu, x, 1);
            x += __shfl_xor_sync(0xffffffffu, x, 2);
            rs[i][r] = x;
        }
    if (t == 0) {
        #pragma unroll
        for (int i = 0; i < 4; i++)
            #pragma unroll
            for (int r = 0; r < 2; r++)
                red[warpN * 128 + warpM * 64 + i * 16 + r * 8 + g] = rs[i][r];
    }
    __syncthreads();
    if (tid < 128)
        g_colsum[uttBase + tid] =
            (red[tid] + red[128 + tid]) + (red[256 + tid] + red[384 + tid]);
}

// ---------------- final loss ------------------------------------------------
__global__ __launch_bounds__(256) void loss_kernel(const float* __restrict__ wp,
                                                   float* __restrict__ out) {
    __shared__ float rsm[8];
    const int j = blockIdx.x * blockDim.x + threadIdx.x;
    const float wv = *wp;
    const float c1 = wv * 1.44269504f;
    const float c0 = -c1;
    float L = 0.0f;
    if (j < NM) {
        float sd = g_sdiag[j];
        float sf = g_sself[j];
        float cs = g_colsum[j] - ex2a(fmaf(sf, c1, c0)) + ex2a(fmaf(sd, c1, c0));
        L = wv * (1.0f - sd) + logf(cs);
    }
    #pragma unroll
    for (int o = 16; o > 0; o >>= 1) L += __shfl_xor_sync(0xffffffffu, L, o);
    const int warp = threadIdx.x >> 5, lane = threadIdx.x & 31;
    if (lane == 0) rsm[warp] = L;
    __syncthreads();
    if (threadIdx.x == 0) {
        float tacc = 0.0f;
        #pragma unroll
        for (int w = 0; w < 8; w++) tacc += rsm[w];
        atomicAdd(out, tacc);
    }
}

// ---------------------------------------------------------------------------
extern "C" void kernel_launch(void* const* d_in, const int* in_sizes, int n_in,
                              void* d_out, int out_size) {
    const float* v  = (const float*)d_in[0];   // [NM, D] fp32
    const float* wp = (const float*)d_in[1];   // scalar w (b cancels analytically)
    float* out = (float*)d_out;

    cudaFuncSetAttribute(gemm_lse_kernel,
                         cudaFuncAttributeMaxDynamicSharedMemorySize, SMEM_SZ);

    init_kernel<<<1, 32>>>(out);
    prep_kernel<<<N_SPK, 256>>>(v);
    gemm_lse_kernel<<<NM / 128, 256, SMEM_SZ>>>(wp);
    loss_kernel<<<NM / 256, 256>>>(wp, out);
}